// round 7
// baseline (speedup 1.0000x reference)
#include <cuda_runtime.h>
#include <cuda_bf16.h>
#include <math.h>
#include <cstdint>

#define BB 8
#define SS 2048
#define DD 768
#define BSD (BB*SS*DD)

// Scratch: Q, K, Vt
__device__ __align__(16) float g_scr[3ll*BSD];

// ---------------- helpers ----------------
__device__ __forceinline__ uint32_t smem_u32(const void* p) {
    uint32_t a;
    asm("{ .reg .u64 t; cvta.to.shared.u64 t, %1; cvt.u32.u64 %0, t; }" : "=r"(a) : "l"(p));
    return a;
}
__device__ __forceinline__ float rna_tf32(float v) {
    uint32_t u; asm("cvt.rna.tf32.f32 %0, %1;" : "=r"(u) : "f"(v));
    return __uint_as_float(u);
}
__device__ __forceinline__ uint32_t rna_tf32_bits(uint32_t v) {
    uint32_t u; asm("cvt.rna.tf32.f32 %0, %1;" : "=r"(u) : "f"(__uint_as_float(v)));
    return u;
}
#define CP_ASYNC16(dst, src) asm volatile("cp.async.cg.shared.global [%0], [%1], 16;" :: "r"(dst), "l"(src))
#define CP_COMMIT() asm volatile("cp.async.commit_group;" ::: "memory")
__device__ __forceinline__ void cp_wait(int n) {
    if (n <= 0)      asm volatile("cp.async.wait_group 0;" ::: "memory");
    else if (n == 1) asm volatile("cp.async.wait_group 1;" ::: "memory");
    else             asm volatile("cp.async.wait_group 2;" ::: "memory");
}

__device__ __forceinline__ void mma1688(float* d, const uint32_t* a, const uint32_t* b) {
    asm volatile(
        "mma.sync.aligned.m16n8k8.row.col.f32.tf32.tf32.f32 "
        "{%0,%1,%2,%3}, {%4,%5,%6,%7}, {%8,%9}, {%0,%1,%2,%3};"
        : "+f"(d[0]), "+f"(d[1]), "+f"(d[2]), "+f"(d[3])
        : "r"(a[0]), "r"(a[1]), "r"(a[2]), "r"(a[3]), "r"(b[0]), "r"(b[1]));
}

// ---------------- tiled tf32 GEMM core ----------------
// CTA tile 256x128, BK=32, 8 warps (4 M x 2 N), warp tile 64x64, NBUF=4.
#define BLK_M 256
#define BLK_N 128
#define BK 32
#define NBUF 4
#define LDA_S 36
#define STAGE_FLOATS (BLK_M*LDA_S + BLK_N*LDA_S)
#define STAGE_BYTES (STAGE_FLOATS*4)
#define SMEM_TOTAL (NBUF*STAGE_BYTES)
#define EPI_LD 132   // multiple of 4 -> float4-aligned rows

__device__ __forceinline__ void load_stage(uint32_t sbase, const float* A, const float* B,
                                           int lda, int ldb, int k0, int tid) {
#pragma unroll
    for (int t = 0; t < 8; t++) {       // A: 256 rows x 8 chunks
        int idx = tid + t * 256;
        int row = idx >> 3, ck = idx & 7;
        CP_ASYNC16(sbase + (uint32_t)(row * LDA_S + ck * 4) * 4,
                   A + (size_t)row * lda + k0 + ck * 4);
    }
    uint32_t bb = sbase + BLK_M * LDA_S * 4;
#pragma unroll
    for (int t = 0; t < 4; t++) {       // B: 128 rows x 8 chunks
        int idx = tid + t * 256;
        int row = idx >> 3, ck = idx & 7;
        CP_ASYNC16(bb + (uint32_t)(row * LDA_S + ck * 4) * 4,
                   B + (size_t)row * ldb + k0 + ck * 4);
    }
}

// core mainloop: accumulates into acc. RND=true applies cvt.rna.tf32 to fragments
// (used by the QKV kernel so raw fp32 x/W inputs behave as pre-rounded tf32).
template <bool RND>
__device__ __forceinline__ void gemm_mainloop(
    const char* smem, uint32_t sb, const float* A, const float* B,
    int Ktot, int lda, int ldb, int tid, int wm, int wn, int lid,
    float acc[4][8][4])
{
    const int iters = Ktot / BK;
    load_stage(sb + 0 * STAGE_BYTES, A, B, lda, ldb, 0, tid);  CP_COMMIT();
    load_stage(sb + 1 * STAGE_BYTES, A, B, lda, ldb, BK, tid); CP_COMMIT();

    for (int i = 0; i < iters; i++) {
        if (i + 2 < iters) {
            load_stage(sb + ((i + 2) % NBUF) * STAGE_BYTES, A, B, lda, ldb, (i + 2) * BK, tid);
            CP_COMMIT();
        }
        int nw = iters - 1 - i; if (nw > 2) nw = 2;
        cp_wait(nw);
        __syncthreads();

        const float* As = (const float*)(smem + (i % NBUF) * STAGE_BYTES);
        const float* Bs = As + BLK_M * LDA_S;
        const int rl = lid >> 2, cl = lid & 3;

#pragma unroll
        for (int ks = 0; ks < BK / 8; ks++) {
            uint32_t af[4][4], bf[8][2];
            const int kk = ks * 8 + cl;
#pragma unroll
            for (int mt = 0; mt < 4; mt++) {
                int ra = wm * 64 + mt * 16 + rl;
                af[mt][0] = __float_as_uint(As[ra * LDA_S + kk]);
                af[mt][1] = __float_as_uint(As[(ra + 8) * LDA_S + kk]);
                af[mt][2] = __float_as_uint(As[ra * LDA_S + kk + 4]);
                af[mt][3] = __float_as_uint(As[(ra + 8) * LDA_S + kk + 4]);
                if (RND) {
#pragma unroll
                    for (int q = 0; q < 4; q++) af[mt][q] = rna_tf32_bits(af[mt][q]);
                }
            }
#pragma unroll
            for (int nt = 0; nt < 8; nt++) {
                int rb = wn * 64 + nt * 8 + rl;
                bf[nt][0] = __float_as_uint(Bs[rb * LDA_S + kk]);
                bf[nt][1] = __float_as_uint(Bs[rb * LDA_S + kk + 4]);
                if (RND) {
                    bf[nt][0] = rna_tf32_bits(bf[nt][0]);
                    bf[nt][1] = rna_tf32_bits(bf[nt][1]);
                }
            }
#pragma unroll
            for (int mt = 0; mt < 4; mt++)
#pragma unroll
                for (int nt = 0; nt < 8; nt++)
                    mma1688(acc[mt][nt], af[mt], bf[nt]);
        }
    }
    __syncthreads();
}

// mode 0: direct register->gmem store (no smem staging)
// mode 1: tf32-rounded store via smem (coalesced)
// mode 2: transposed (Vt) rounded store via smem
__device__ __forceinline__ void epilogue_store(
    char* smem, float* C, int ldc, int m0, int n0,
    int tid, int wm, int wn, int lid, float alpha, int mode,
    float acc[4][8][4])
{
    const int rl = lid >> 2, cl = lid & 3;

    if (mode == 0) {
        // direct: each thread stores float2 pairs; 32B-sector aligned
#pragma unroll
        for (int mt = 0; mt < 4; mt++) {
#pragma unroll
            for (int nt = 0; nt < 8; nt++) {
                int r = wm * 64 + mt * 16 + rl;
                int c = wn * 64 + nt * 8 + 2 * cl;
                float2 lo = make_float2(alpha * acc[mt][nt][0], alpha * acc[mt][nt][1]);
                float2 hi = make_float2(alpha * acc[mt][nt][2], alpha * acc[mt][nt][3]);
                *(float2*)(C + (size_t)(m0 + r) * ldc + n0 + c) = lo;
                *(float2*)(C + (size_t)(m0 + r + 8) * ldc + n0 + c) = hi;
            }
        }
        return;
    }

    float* epis = (float*)smem;
#pragma unroll
    for (int mt = 0; mt < 4; mt++) {
#pragma unroll
        for (int nt = 0; nt < 8; nt++) {
            int r = wm * 64 + mt * 16 + rl;
            int c = wn * 64 + nt * 8 + 2 * cl;
            float v0 = rna_tf32(alpha * acc[mt][nt][0]);
            float v1 = rna_tf32(alpha * acc[mt][nt][1]);
            float v2 = rna_tf32(alpha * acc[mt][nt][2]);
            float v3 = rna_tf32(alpha * acc[mt][nt][3]);
            epis[r * EPI_LD + c] = v0;
            epis[r * EPI_LD + c + 1] = v1;
            epis[(r + 8) * EPI_LD + c] = v2;
            epis[(r + 8) * EPI_LD + c + 1] = v3;
        }
    }
    __syncthreads();

    if (mode == 1) {
#pragma unroll
        for (int it = 0; it < 32; it++) {
            int idx = tid + it * 256;
            int r = idx >> 5, c4 = (idx & 31) * 4;
            float4 v = *(const float4*)(epis + r * EPI_LD + c4);
            *(float4*)(C + (size_t)(m0 + r) * ldc + n0 + c4) = v;
        }
    } else {
        // C is Vt[B][D][S]
        const int bb = m0 >> 11, s0 = m0 & 2047;
        float* T = C + (size_t)bb * DD * SS + s0;
#pragma unroll
        for (int it = 0; it < 128; it++) {
            int idx = tid + it * 256;
            int r = idx & 255, c = idx >> 8;
            T[(size_t)(n0 + c) * SS + r] = epis[r * EPI_LD + c];
        }
    }
}

// ---------------- generic GEMM-NT (scores, AV): mode 0 ----------------
__global__ void __launch_bounds__(256, 1) gemm_tc(
    const float* __restrict__ A, const float* __restrict__ B, float* __restrict__ C,
    int Ktot, long long strA, long long strB, long long strC,
    int lda, int ldb, int ldc, float alpha)
{
    extern __shared__ char smem[];
    const uint32_t sb = smem_u32(smem);
    const int tid = threadIdx.x, wid = tid >> 5, lid = tid & 31;
    const int wm = wid & 3, wn = wid >> 2;
    const int m0 = blockIdx.x * BLK_M, n0 = blockIdx.y * BLK_N;

    A += blockIdx.z * strA + (size_t)m0 * lda;
    B += blockIdx.z * strB + (size_t)n0 * ldb;
    C += blockIdx.z * strC;

    float acc[4][8][4];
#pragma unroll
    for (int i = 0; i < 4; i++)
#pragma unroll
        for (int j = 0; j < 8; j++)
#pragma unroll
            for (int k = 0; k < 4; k++) acc[i][j][k] = 0.f;

    gemm_mainloop<false>(smem, sb, A, B, Ktot, lda, ldb, tid, wm, wn, lid, acc);
    epilogue_store(smem, C, ldc, m0, n0, tid, wm, wn, lid, alpha, 0, acc);
}

// ---------------- fused QKV projection (z selects weight/output) ----------------
// Reads RAW x and W; rounds fragments to tf32 in-register (== pre-rounding pass).
__global__ void __launch_bounds__(256, 1) gemm_qkv(
    const float* __restrict__ x,
    const float* __restrict__ Wq, const float* __restrict__ Wk, const float* __restrict__ Wv,
    float* __restrict__ Q, float* __restrict__ Km, float* __restrict__ Vt)
{
    extern __shared__ char smem[];
    const uint32_t sb = smem_u32(smem);
    const int tid = threadIdx.x, wid = tid >> 5, lid = tid & 31;
    const int wm = wid & 3, wn = wid >> 2;
    const int m0 = blockIdx.x * BLK_M, n0 = blockIdx.y * BLK_N;
    const int z = blockIdx.z;

    const float* A = x + (size_t)m0 * DD;
    const float* B = ((z == 0) ? Wq : (z == 1) ? Wk : Wv) + (size_t)n0 * DD;
    float* C = (z == 0) ? Q : (z == 1) ? Km : Vt;
    const int mode = (z == 2) ? 2 : 1;

    float acc[4][8][4];
#pragma unroll
    for (int i = 0; i < 4; i++)
#pragma unroll
        for (int j = 0; j < 8; j++)
#pragma unroll
            for (int k = 0; k < 4; k++) acc[i][j][k] = 0.f;

    gemm_mainloop<true>(smem, sb, A, B, DD, DD, DD, tid, wm, wn, lid, acc);
    epilogue_store(smem, C, DD, m0, n0, tid, wm, wn, lid, 1.0f, mode, acc);
}

// ---------------- softmax (in place, tf32-rounded output, float4) ----------------
__global__ __launch_bounds__(256) void softmax_kernel(float* __restrict__ attn) {
    float4* p = (float4*)(attn + (size_t)blockIdx.x * SS);
    const int t = threadIdx.x;
    const int lid = t & 31, wrp = t >> 5;
    __shared__ float red[8];

    float4 v0 = p[t], v1 = p[t + 256];
    float m = fmaxf(fmaxf(fmaxf(v0.x, v0.y), fmaxf(v0.z, v0.w)),
                    fmaxf(fmaxf(v1.x, v1.y), fmaxf(v1.z, v1.w)));
#pragma unroll
    for (int s = 16; s > 0; s >>= 1) m = fmaxf(m, __shfl_xor_sync(0xffffffffu, m, s));
    if (lid == 0) red[wrp] = m;
    __syncthreads();
    m = fmaxf(fmaxf(fmaxf(red[0], red[1]), fmaxf(red[2], red[3])),
              fmaxf(fmaxf(red[4], red[5]), fmaxf(red[6], red[7])));
    __syncthreads();

    v0.x = __expf(v0.x - m); v0.y = __expf(v0.y - m); v0.z = __expf(v0.z - m); v0.w = __expf(v0.w - m);
    v1.x = __expf(v1.x - m); v1.y = __expf(v1.y - m); v1.z = __expf(v1.z - m); v1.w = __expf(v1.w - m);
    float sum = (v0.x + v0.y) + (v0.z + v0.w) + (v1.x + v1.y) + (v1.z + v1.w);
#pragma unroll
    for (int s = 16; s > 0; s >>= 1) sum += __shfl_xor_sync(0xffffffffu, sum, s);
    if (lid == 0) red[wrp] = sum;
    __syncthreads();
    sum = (red[0] + red[1]) + (red[2] + red[3]) + (red[4] + red[5]) + (red[6] + red[7]);
    float inv = 1.f / sum;

    v0.x = rna_tf32(v0.x * inv); v0.y = rna_tf32(v0.y * inv);
    v0.z = rna_tf32(v0.z * inv); v0.w = rna_tf32(v0.w * inv);
    v1.x = rna_tf32(v1.x * inv); v1.y = rna_tf32(v1.y * inv);
    v1.z = rna_tf32(v1.z * inv); v1.w = rna_tf32(v1.w * inv);
    p[t] = v0; p[t + 256] = v1;
}

// ---------------- launcher ----------------
extern "C" void kernel_launch(void* const* d_in, const int* in_sizes, int n_in,
                              void* d_out, int out_size)
{
    const float* x  = (const float*)d_in[0];
    const float* Wq = (const float*)d_in[1];
    const float* Wk = (const float*)d_in[2];
    const float* Wv = (const float*)d_in[3];

    float* out_wv   = (float*)d_out;
    float* out_attn = (float*)d_out + BSD;

    float* base = nullptr;
    cudaGetSymbolAddress((void**)&base, g_scr);
    float* Q   = base;
    float* Km  = base + (long long)BSD;
    float* Vt  = base + 2ll * BSD;

    static int smem_set = 0;
    if (!smem_set) {
        cudaFuncSetAttribute(gemm_tc,  cudaFuncAttributeMaxDynamicSharedMemorySize, SMEM_TOTAL);
        cudaFuncSetAttribute(gemm_qkv, cudaFuncAttributeMaxDynamicSharedMemorySize, SMEM_TOTAL);
        smem_set = 1;
    }

    // 1) fused QKV projections: one launch, z = {Q, K, Vt}; tf32 rounding in-kernel
    {
        dim3 grid(BB * SS / BLK_M, DD / BLK_N, 3);
        gemm_qkv<<<grid, 256, SMEM_TOTAL>>>(x, Wq, Wk, Wv, Q, Km, Vt);
    }

    // 2) scores = Q K^T / sqrt(D) -> attn (unnormalized)
    {
        dim3 grid(SS / BLK_M, SS / BLK_N, BB);
        gemm_tc<<<grid, 256, SMEM_TOTAL>>>(Q, Km, out_attn, DD,
                                           (long long)SS * DD, (long long)SS * DD, (long long)SS * SS,
                                           DD, DD, SS, 1.0f / sqrtf((float)DD));
    }

    // 3) softmax (tf32-rounded weights)
    softmax_kernel<<<BB * SS, 256>>>(out_attn);

    // 4) weighted = attn @ V (NT against Vt)
    {
        dim3 grid(SS / BLK_M, DD / BLK_N, BB);
        gemm_tc<<<grid, 256, SMEM_TOTAL>>>(out_attn, Vt, out_wv, SS,
                                           (long long)SS * SS, (long long)DD * SS, (long long)SS * DD,
                                           SS, SS, DD, 1.0f);
    }
}

// round 8
// speedup vs baseline: 1.0226x; 1.0226x over previous
#include <cuda_runtime.h>
#include <cuda_bf16.h>
#include <math.h>
#include <cstdint>

#define BB 8
#define SS 2048
#define DD 768
#define BSD (BB*SS*DD)
#define BSS (1ll*BB*SS*SS)

// Scratch layout: Q, Km, Vt, xr, Wr[3], gsum, inv, t
__device__ __align__(16) float g_scr[4ll*BSD + 3ll*DD*DD + 2ll*BB*SS + BSS];

#define OFF_Q    0ll
#define OFF_K    (1ll*BSD)
#define OFF_VT   (2ll*BSD)
#define OFF_XR   (3ll*BSD)
#define OFF_WR   (4ll*BSD)
#define OFF_GSUM (4ll*BSD + 3ll*DD*DD)
#define OFF_INV  (OFF_GSUM + BB*SS)
#define OFF_T    (OFF_INV + BB*SS)

// ---------------- helpers ----------------
__device__ __forceinline__ uint32_t smem_u32(const void* p) {
    uint32_t a;
    asm("{ .reg .u64 t; cvta.to.shared.u64 t, %1; cvt.u32.u64 %0, t; }" : "=r"(a) : "l"(p));
    return a;
}
__device__ __forceinline__ float rna_tf32(float v) {
    uint32_t u; asm("cvt.rna.tf32.f32 %0, %1;" : "=r"(u) : "f"(v));
    return __uint_as_float(u);
}
#define CP_ASYNC16(dst, src) asm volatile("cp.async.cg.shared.global [%0], [%1], 16;" :: "r"(dst), "l"(src))
#define CP_COMMIT() asm volatile("cp.async.commit_group;" ::: "memory")
__device__ __forceinline__ void cp_wait(int n) {
    if (n <= 0)      asm volatile("cp.async.wait_group 0;" ::: "memory");
    else if (n == 1) asm volatile("cp.async.wait_group 1;" ::: "memory");
    else             asm volatile("cp.async.wait_group 2;" ::: "memory");
}

__device__ __forceinline__ void mma1688(float* d, const uint32_t* a, const uint32_t* b) {
    asm volatile(
        "mma.sync.aligned.m16n8k8.row.col.f32.tf32.tf32.f32 "
        "{%0,%1,%2,%3}, {%4,%5,%6,%7}, {%8,%9}, {%0,%1,%2,%3};"
        : "+f"(d[0]), "+f"(d[1]), "+f"(d[2]), "+f"(d[3])
        : "r"(a[0]), "r"(a[1]), "r"(a[2]), "r"(a[3]), "r"(b[0]), "r"(b[1]));
}

// ---------------- tiled tf32 GEMM core (round-4/6 config) ----------------
#define BLK_M 256
#define BLK_N 128
#define BK 32
#define NBUF 4
#define LDA_S 36
#define STAGE_FLOATS (BLK_M*LDA_S + BLK_N*LDA_S)
#define STAGE_BYTES (STAGE_FLOATS*4)
#define SMEM_TOTAL (NBUF*STAGE_BYTES)
#define EPI_LD 132

__device__ __forceinline__ void load_stage(uint32_t sbase, const float* A, const float* B,
                                           int lda, int ldb, int k0, int tid) {
#pragma unroll
    for (int t = 0; t < 8; t++) {       // A: 256 rows x 8 chunks
        int idx = tid + t * 256;
        int row = idx >> 3, ck = idx & 7;
        CP_ASYNC16(sbase + (uint32_t)(row * LDA_S + ck * 4) * 4,
                   A + (size_t)row * lda + k0 + ck * 4);
    }
    uint32_t bb = sbase + BLK_M * LDA_S * 4;
#pragma unroll
    for (int t = 0; t < 4; t++) {       // B: 128 rows x 8 chunks
        int idx = tid + t * 256;
        int row = idx >> 3, ck = idx & 7;
        CP_ASYNC16(bb + (uint32_t)(row * LDA_S + ck * 4) * 4,
                   B + (size_t)row * ldb + k0 + ck * 4);
    }
}

// AVW: while a stage is resident, the owning slice CTA writes attn = t*inv for
// that 32-column band (stage s owned when s % 6 == slice).
template <bool AVW>
__device__ __forceinline__ void gemm_mainloop(
    const char* smem, uint32_t sb, const float* A, const float* B,
    int Ktot, int lda, int ldb, int tid, int wm, int wn, int lid,
    float acc[4][8][4],
    float* attn_base, const float* invp, int slice)
{
    const int iters = Ktot / BK;
    load_stage(sb + 0 * STAGE_BYTES, A, B, lda, ldb, 0, tid);  CP_COMMIT();
    load_stage(sb + 1 * STAGE_BYTES, A, B, lda, ldb, BK, tid); CP_COMMIT();

    for (int i = 0; i < iters; i++) {
        if (i + 2 < iters) {
            load_stage(sb + ((i + 2) % NBUF) * STAGE_BYTES, A, B, lda, ldb, (i + 2) * BK, tid);
            CP_COMMIT();
        }
        int nw = iters - 1 - i; if (nw > 2) nw = 2;
        cp_wait(nw);
        __syncthreads();

        const float* As = (const float*)(smem + (i % NBUF) * STAGE_BYTES);
        const float* Bs = As + BLK_M * LDA_S;
        const int rl = lid >> 2, cl = lid & 3;

        if (AVW && (i % 6) == slice) {
            // write attn slice for this 32-col band from the resident smem tile
            float* dst = attn_base + (size_t)(i * BK);
            const int r0 = tid >> 3, c4 = tid & 7;
#pragma unroll
            for (int rr = r0; rr < BLK_M; rr += 32) {
                float4 v = *(const float4*)(As + rr * LDA_S + c4 * 4);
                float iv = invp[rr];
                v.x *= iv; v.y *= iv; v.z *= iv; v.w *= iv;
                *(float4*)(dst + (size_t)rr * SS + c4 * 4) = v;
            }
        }

#pragma unroll
        for (int ks = 0; ks < BK / 8; ks++) {
            uint32_t af[4][4], bf[8][2];
            const int kk = ks * 8 + cl;
#pragma unroll
            for (int mt = 0; mt < 4; mt++) {
                int ra = wm * 64 + mt * 16 + rl;
                af[mt][0] = __float_as_uint(As[ra * LDA_S + kk]);
                af[mt][1] = __float_as_uint(As[(ra + 8) * LDA_S + kk]);
                af[mt][2] = __float_as_uint(As[ra * LDA_S + kk + 4]);
                af[mt][3] = __float_as_uint(As[(ra + 8) * LDA_S + kk + 4]);
            }
#pragma unroll
            for (int nt = 0; nt < 8; nt++) {
                int rb = wn * 64 + nt * 8 + rl;
                bf[nt][0] = __float_as_uint(Bs[rb * LDA_S + kk]);
                bf[nt][1] = __float_as_uint(Bs[rb * LDA_S + kk + 4]);
            }
#pragma unroll
            for (int mt = 0; mt < 4; mt++)
#pragma unroll
                for (int nt = 0; nt < 8; nt++)
                    mma1688(acc[mt][nt], af[mt], bf[nt]);
        }
    }
    __syncthreads();
}

// stage values (already transformed) to smem, then coalesced copy / transpose
__device__ __forceinline__ void epi_copy_plain(
    const char* smem, float* C, int ldc, int m0, int n0, int tid)
{
    const float* epis = (const float*)smem;
#pragma unroll
    for (int it = 0; it < 32; it++) {
        int idx = tid + it * 256;
        int r = idx >> 5, c4 = (idx & 31) * 4;
        float4 v = *(const float4*)(epis + r * EPI_LD + c4);
        *(float4*)(C + (size_t)(m0 + r) * ldc + n0 + c4) = v;
    }
}

// ---------------- fused QKV projection (round-6 style: pre-rounded inputs) ----------------
__global__ void __launch_bounds__(256, 1) gemm_qkv(
    const float* __restrict__ xr, const float* __restrict__ Wr,
    float* __restrict__ Q, float* __restrict__ Km, float* __restrict__ Vt)
{
    extern __shared__ char smem[];
    const uint32_t sb = smem_u32(smem);
    const int tid = threadIdx.x, wid = tid >> 5, lid = tid & 31;
    const int wm = wid & 3, wn = wid >> 2;
    const int m0 = blockIdx.x * BLK_M, n0 = blockIdx.y * BLK_N;
    const int z = blockIdx.z;

    const float* A = xr + (size_t)m0 * DD;
    const float* B = Wr + (size_t)z * DD * DD + (size_t)n0 * DD;
    float* C = (z == 0) ? Q : (z == 1) ? Km : Vt;

    float acc[4][8][4];
#pragma unroll
    for (int i = 0; i < 4; i++)
#pragma unroll
        for (int j = 0; j < 8; j++)
#pragma unroll
            for (int k = 0; k < 4; k++) acc[i][j][k] = 0.f;

    gemm_mainloop<false>(smem, sb, A, B, DD, DD, DD, tid, wm, wn, lid, acc, nullptr, nullptr, 0);

    // epilogue: rna-rounded stage
    float* epis = (float*)smem;
    const int rl = lid >> 2, cl = lid & 3;
#pragma unroll
    for (int mt = 0; mt < 4; mt++) {
#pragma unroll
        for (int nt = 0; nt < 8; nt++) {
            int r = wm * 64 + mt * 16 + rl;
            int c = wn * 64 + nt * 8 + 2 * cl;
            epis[r * EPI_LD + c]           = rna_tf32(acc[mt][nt][0]);
            epis[r * EPI_LD + c + 1]       = rna_tf32(acc[mt][nt][1]);
            epis[(r + 8) * EPI_LD + c]     = rna_tf32(acc[mt][nt][2]);
            epis[(r + 8) * EPI_LD + c + 1] = rna_tf32(acc[mt][nt][3]);
        }
    }
    __syncthreads();

    if (z != 2) {
        epi_copy_plain(smem, C, DD, m0, n0, tid);
    } else {
        // Vt[B][D][S] transposed store
        const int bb = m0 >> 11, s0 = m0 & 2047;
        float* T = C + (size_t)bb * DD * SS + s0;
#pragma unroll
        for (int it = 0; it < 128; it++) {
            int idx = tid + it * 256;
            int r = idx & 255, c = idx >> 8;
            T[(size_t)(n0 + c) * SS + r] = epis[r * EPI_LD + c];
        }
    }
}

// ---------------- scores: t = rna(exp(QK/sqrt(D))) + row sums ----------------
__global__ void __launch_bounds__(256, 1) gemm_scores(
    const float* __restrict__ Q, const float* __restrict__ Km,
    float* __restrict__ T, float* __restrict__ gsum, float alpha)
{
    extern __shared__ char smem[];
    const uint32_t sb = smem_u32(smem);
    const int tid = threadIdx.x, wid = tid >> 5, lid = tid & 31;
    const int wm = wid & 3, wn = wid >> 2;
    const int m0 = blockIdx.x * BLK_M, n0 = blockIdx.y * BLK_N;
    const int bz = blockIdx.z;

    const float* A = Q  + (size_t)bz * SS * DD + (size_t)m0 * DD;
    const float* B = Km + (size_t)bz * SS * DD + (size_t)n0 * DD;
    float* C = T + (size_t)bz * SS * SS;

    float acc[4][8][4];
#pragma unroll
    for (int i = 0; i < 4; i++)
#pragma unroll
        for (int j = 0; j < 8; j++)
#pragma unroll
            for (int k = 0; k < 4; k++) acc[i][j][k] = 0.f;

    gemm_mainloop<false>(smem, sb, A, B, DD, DD, DD, tid, wm, wn, lid, acc, nullptr, nullptr, 0);

    // epilogue: t = rna(exp(alpha*acc)); stage, copy, row-sum + atomic
    float* epis = (float*)smem;
    const int rl = lid >> 2, cl = lid & 3;
#pragma unroll
    for (int mt = 0; mt < 4; mt++) {
#pragma unroll
        for (int nt = 0; nt < 8; nt++) {
            int r = wm * 64 + mt * 16 + rl;
            int c = wn * 64 + nt * 8 + 2 * cl;
            epis[r * EPI_LD + c]           = rna_tf32(__expf(alpha * acc[mt][nt][0]));
            epis[r * EPI_LD + c + 1]       = rna_tf32(__expf(alpha * acc[mt][nt][1]));
            epis[(r + 8) * EPI_LD + c]     = rna_tf32(__expf(alpha * acc[mt][nt][2]));
            epis[(r + 8) * EPI_LD + c + 1] = rna_tf32(__expf(alpha * acc[mt][nt][3]));
        }
    }
    __syncthreads();

    epi_copy_plain(smem, C, SS, m0, n0, tid);

    // row sum: thread tid owns row tid
    {
        float s = 0.f;
        const float* row = epis + tid * EPI_LD;
#pragma unroll
        for (int c4 = 0; c4 < 32; c4++) {
            float4 v = *(const float4*)(row + c4 * 4);
            s += (v.x + v.y) + (v.z + v.w);
        }
        atomicAdd(&gsum[(size_t)bz * SS + m0 + tid], s);
    }
}

// ---------------- AV: wv = inv * (t @ V), attn = t * inv written in mainloop ----------------
__global__ void __launch_bounds__(256, 1) gemm_av(
    const float* __restrict__ T, const float* __restrict__ Vt,
    float* __restrict__ Wv, float* __restrict__ Attn, const float* __restrict__ Inv)
{
    extern __shared__ char smem[];
    const uint32_t sb = smem_u32(smem);
    const int tid = threadIdx.x, wid = tid >> 5, lid = tid & 31;
    const int wm = wid & 3, wn = wid >> 2;
    const int m0 = blockIdx.x * BLK_M, n0 = blockIdx.y * BLK_N;
    const int bz = blockIdx.z;

    const float* A = T  + (size_t)bz * SS * SS + (size_t)m0 * SS;
    const float* B = Vt + (size_t)bz * DD * SS + (size_t)n0 * SS;
    float* C = Wv + (size_t)bz * SS * DD;
    float* attn_base = Attn + (size_t)bz * SS * SS + (size_t)m0 * SS;
    const float* invp = Inv + (size_t)bz * SS + m0;

    float acc[4][8][4];
#pragma unroll
    for (int i = 0; i < 4; i++)
#pragma unroll
        for (int j = 0; j < 8; j++)
#pragma unroll
            for (int k = 0; k < 4; k++) acc[i][j][k] = 0.f;

    gemm_mainloop<true>(smem, sb, A, B, SS, SS, SS, tid, wm, wn, lid, acc,
                        attn_base, invp, (int)blockIdx.y);

    // epilogue: per-row inv scaling, staged, coalesced store
    float* epis = (float*)smem;
    const int rl = lid >> 2, cl = lid & 3;
#pragma unroll
    for (int mt = 0; mt < 4; mt++) {
        int r = wm * 64 + mt * 16 + rl;
        float iv0 = invp[r], iv1 = invp[r + 8];
#pragma unroll
        for (int nt = 0; nt < 8; nt++) {
            int c = wn * 64 + nt * 8 + 2 * cl;
            epis[r * EPI_LD + c]           = iv0 * acc[mt][nt][0];
            epis[r * EPI_LD + c + 1]       = iv0 * acc[mt][nt][1];
            epis[(r + 8) * EPI_LD + c]     = iv1 * acc[mt][nt][2];
            epis[(r + 8) * EPI_LD + c + 1] = iv1 * acc[mt][nt][3];
        }
    }
    __syncthreads();

    epi_copy_plain(smem, C, DD, m0, n0, tid);
}

// ---------------- small kernels ----------------
__global__ __launch_bounds__(256) void round_tf32_kernel(const float* __restrict__ in,
                                                         float* __restrict__ out, int n4) {
    int i = blockIdx.x * 256 + threadIdx.x;
    if (i < n4) {
        float4 v = ((const float4*)in)[i];
        v.x = rna_tf32(v.x); v.y = rna_tf32(v.y); v.z = rna_tf32(v.z); v.w = rna_tf32(v.w);
        ((float4*)out)[i] = v;
    }
}
__global__ __launch_bounds__(256) void zero_kernel(float* __restrict__ p, int n) {
    int i = blockIdx.x * 256 + threadIdx.x;
    if (i < n) p[i] = 0.f;
}
__global__ __launch_bounds__(256) void recip_kernel(const float* __restrict__ s,
                                                    float* __restrict__ inv, int n) {
    int i = blockIdx.x * 256 + threadIdx.x;
    if (i < n) inv[i] = 1.f / s[i];
}

// ---------------- launcher ----------------
extern "C" void kernel_launch(void* const* d_in, const int* in_sizes, int n_in,
                              void* d_out, int out_size)
{
    const float* x  = (const float*)d_in[0];
    const float* Wq = (const float*)d_in[1];
    const float* Wk = (const float*)d_in[2];
    const float* Wv = (const float*)d_in[3];

    float* out_wv   = (float*)d_out;
    float* out_attn = (float*)d_out + BSD;

    float* base = nullptr;
    cudaGetSymbolAddress((void**)&base, g_scr);
    float* Q    = base + OFF_Q;
    float* Km   = base + OFF_K;
    float* Vt   = base + OFF_VT;
    float* xr   = base + OFF_XR;
    float* Wr   = base + OFF_WR;
    float* gsum = base + OFF_GSUM;
    float* inv  = base + OFF_INV;
    float* Tm   = base + OFF_T;

    static int smem_set = 0;
    if (!smem_set) {
        cudaFuncSetAttribute(gemm_qkv,    cudaFuncAttributeMaxDynamicSharedMemorySize, SMEM_TOTAL);
        cudaFuncSetAttribute(gemm_scores, cudaFuncAttributeMaxDynamicSharedMemorySize, SMEM_TOTAL);
        cudaFuncSetAttribute(gemm_av,     cudaFuncAttributeMaxDynamicSharedMemorySize, SMEM_TOTAL);
        smem_set = 1;
    }

    // 0) zero row sums; round inputs to tf32
    zero_kernel<<<BB * SS / 256, 256>>>(gsum, BB * SS);
    round_tf32_kernel<<<(BSD / 4 + 255) / 256, 256>>>(x, xr, BSD / 4);
    round_tf32_kernel<<<(DD * DD / 4 + 255) / 256, 256>>>(Wq, Wr,               DD * DD / 4);
    round_tf32_kernel<<<(DD * DD / 4 + 255) / 256, 256>>>(Wk, Wr + DD * DD,     DD * DD / 4);
    round_tf32_kernel<<<(DD * DD / 4 + 255) / 256, 256>>>(Wv, Wr + 2 * DD * DD, DD * DD / 4);

    // 1) fused QKV projections
    {
        dim3 grid(BB * SS / BLK_M, DD / BLK_N, 3);
        gemm_qkv<<<grid, 256, SMEM_TOTAL>>>(xr, Wr, Q, Km, Vt);
    }

    // 2) t = rna(exp(Q K^T / sqrt(D))), row sums via atomics
    {
        dim3 grid(SS / BLK_M, SS / BLK_N, BB);
        gemm_scores<<<grid, 256, SMEM_TOTAL>>>(Q, Km, Tm, gsum, 1.0f / sqrtf((float)DD));
    }

    // 3) inv = 1/gsum
    recip_kernel<<<BB * SS / 256, 256>>>(gsum, inv, BB * SS);

    // 4) wv = inv*(t @ V); attn = t*inv written from resident tiles in-mainloop
    {
        dim3 grid(SS / BLK_M, DD / BLK_N, BB);
        gemm_av<<<grid, 256, SMEM_TOTAL>>>(Tm, Vt, out_wv, out_attn, inv);
    }
}